// round 1
// baseline (speedup 1.0000x reference)
#include <cuda_runtime.h>

#define M_PILLARS 16384
#define N_POINTS  4096
#define C_FEAT    64
#define RADIUS2   1.0f
#define VX        0.16f
#define VY        0.16f
#define PCX       0.0f
#define PCY       -25.6f

__global__ __launch_bounds__(256)
void query_fusion_kernel(const float* __restrict__ pillar_feature,
                         const int*   __restrict__ coors,
                         const float* __restrict__ seg_feats,
                         const float* __restrict__ seg_points,
                         float*       __restrict__ out) {
    __shared__ float2 pts[N_POINTS];   // 32 KB

    const int tid = threadIdx.x;
    // Stage point xy into shared (coalesced-ish: 3-stride source)
    for (int i = tid; i < N_POINTS; i += blockDim.x) {
        pts[i] = make_float2(seg_points[i * 3 + 0], seg_points[i * 3 + 1]);
    }
    __syncthreads();

    const int warp = tid >> 5;
    const int lane = tid & 31;
    const int m = blockIdx.x * (blockDim.x >> 5) + warp;
    if (m >= M_PILLARS) return;

    // Pillar center xy from coors row [0,0,y,x]
    const float px = ((float)coors[m * 4 + 3] + 0.5f) * VX + PCX;
    const float py = ((float)coors[m * 4 + 2] + 0.5f) * VY + PCY;

    // Ordered ball query: first 4 in-radius indices (scan order)
    int i0 = 0, i1 = 0, i2 = 0, i3 = 0;
    int found = 0;

    for (int base = 0; base < N_POINTS; base += 32) {
        float2 p = pts[base + lane];
        float dx = px - p.x;
        float dy = py - p.y;
        bool within = (dx * dx + dy * dy) < RADIUS2;
        unsigned mask = __ballot_sync(0xffffffffu, within);
        // mask is uniform across the warp; extraction loop is warp-uniform.
        while (mask) {
            int b = base + (__ffs(mask) - 1);
            mask &= (mask - 1);
            if      (found == 0) i0 = b;
            else if (found == 1) i1 = b;
            else if (found == 2) i2 = b;
            else                 i3 = b;
            found++;
            if (found == 4) break;
        }
        if (found == 4) break;
    }

    // Pad with first found index (all-zero if none found)
    if (found == 0) { i0 = i1 = i2 = i3 = 0; }
    else {
        if (found < 2) i1 = i0;
        if (found < 3) i2 = i0;
        if (found < 4) i3 = i0;
    }

    // Reference quirk: flag = (sum of indices) > 0
    const bool flag = (i0 + i1 + i2 + i3) > 0;

    // Feature fuse: 64 channels, 2 per lane, coalesced
    const size_t mrow = (size_t)m * C_FEAT;
    float v0 = pillar_feature[mrow + lane];
    float v1 = pillar_feature[mrow + lane + 32];

    if (flag) {
        const size_t r0 = (size_t)i0 * C_FEAT;
        const size_t r1 = (size_t)i1 * C_FEAT;
        const size_t r2 = (size_t)i2 * C_FEAT;
        const size_t r3 = (size_t)i3 * C_FEAT;

        float a0 = seg_feats[r0 + lane];
        float a1 = seg_feats[r1 + lane];
        float a2 = seg_feats[r2 + lane];
        float a3 = seg_feats[r3 + lane];
        float b0 = seg_feats[r0 + lane + 32];
        float b1 = seg_feats[r1 + lane + 32];
        float b2 = seg_feats[r2 + lane + 32];
        float b3 = seg_feats[r3 + lane + 32];

        v0 += fmaxf(fmaxf(a0, a1), fmaxf(a2, a3));
        v1 += fmaxf(fmaxf(b0, b1), fmaxf(b2, b3));
    }

    out[mrow + lane]      = v0;
    out[mrow + lane + 32] = v1;
}

extern "C" void kernel_launch(void* const* d_in, const int* in_sizes, int n_in,
                              void* d_out, int out_size) {
    const float* pillar_feature = (const float*)d_in[0];  // [M, 64]
    const int*   coors          = (const int*)  d_in[1];  // [M, 4]
    const float* seg_feats      = (const float*)d_in[2];  // [N, 64]
    const float* seg_points     = (const float*)d_in[3];  // [N, 3]
    float* out = (float*)d_out;                            // [M, 64]

    const int warps_per_block = 8;          // 256 threads
    const int blocks = M_PILLARS / warps_per_block;  // 2048
    query_fusion_kernel<<<blocks, 256>>>(pillar_feature, coors, seg_feats,
                                         seg_points, out);
}